// round 7
// baseline (speedup 1.0000x reference)
#include <cuda_runtime.h>
#include <cstdint>

// Problem constants
#define B_   8
#define H_   224
#define HW_  (H_*H_)          // 50176
#define OC_  32
#define NH_  8
#define HD_  4
#define NPIX (B_*HW_)         // 401408
#define X1_N (B_*OC_*HW_)     // 12845056
#define QKV_N (B_*96*HW_)     // 38535168
#define ATT_N (B_*NH_*HD_*H_*H_) // 12845056

// Scratch (static device globals; no allocation allowed)
__device__ float g_x1[X1_N];
__device__ float g_qkv[QKV_N];
__device__ float g_A2[X1_N];
__device__ int   g_jidx[B_*NH_*HD_*H_];   // 57344
__device__ float g_wc[32*32];
__device__ float g_bc[32];
__device__ float g_sum[32];
__device__ float g_sq[32];
__device__ float g_wt[96*32*16];          // winograd-transformed qkv weights (only v rows used)

// ---------------------------------------------------------------- prep
__global__ void k_prep(const float* __restrict__ upd_w, const float* __restrict__ proj_w,
                       const float* __restrict__ proj_b, const float* __restrict__ upd_b) {
    int t = threadIdx.x;            // 1024 threads
    int o = t >> 5, c = t & 31;
    float s = 0.f;
    #pragma unroll
    for (int m = 0; m < 32; m++) s += upd_w[o*32+m] * proj_w[m*32+c];
    g_wc[o*32+c] = s;
    if (c == 0) {
        float bsum = upd_b[o];
        #pragma unroll
        for (int m = 0; m < 32; m++) bsum += upd_w[o*32+m] * proj_b[m];
        g_bc[o] = bsum;
    }
    if (t < 32) { g_sum[t] = 0.f; g_sq[t] = 0.f; }
}

// ---------------------------------------------------------------- winograd weight transform
// W~ = G g G^T, G = [[1,0,0],[.5,.5,.5],[.5,-.5,.5],[0,0,1]]
__global__ void k_wprep(const float* __restrict__ qkv_w) {
    int id = blockIdx.x * 256 + threadIdx.x;   // 12*256 = 3072 exact
    const float* gp = qkv_w + id * 9;
    float g0[3][3];
    #pragma unroll
    for (int r = 0; r < 3; r++)
        #pragma unroll
        for (int c = 0; c < 3; c++) g0[r][c] = gp[r*3 + c];
    float P[4][3];
    #pragma unroll
    for (int c = 0; c < 3; c++) {
        P[0][c] = g0[0][c];
        P[1][c] = 0.5f*(g0[0][c] + g0[1][c] + g0[2][c]);
        P[2][c] = 0.5f*(g0[0][c] - g0[1][c] + g0[2][c]);
        P[3][c] = g0[2][c];
    }
    #pragma unroll
    for (int r = 0; r < 4; r++) {
        g_wt[id*16 + r*4 + 0] = P[r][0];
        g_wt[id*16 + r*4 + 1] = 0.5f*(P[r][0] + P[r][1] + P[r][2]);
        g_wt[id*16 + r*4 + 2] = 0.5f*(P[r][0] - P[r][1] + P[r][2]);
        g_wt[id*16 + r*4 + 3] = P[r][2];
    }
}

// ---------------------------------------------------------------- zero att
__global__ void k_zero(float4* __restrict__ p) {
    int i = blockIdx.x * 256 + threadIdx.x;   // grid covers ATT_N/4 exactly
    p[i] = make_float4(0.f, 0.f, 0.f, 0.f);
}

// ---------------------------------------------------------------- conv_in: 3->32, 3x3, pad 1
__global__ __launch_bounds__(256) void k_conv_in(const float* __restrict__ x,
                                                 const float* __restrict__ w,
                                                 const float* __restrict__ bias) {
    __shared__ float ws[32*27];
    __shared__ float bs[32];
    int t = threadIdx.x;
    for (int i = t; i < 864; i += 256) ws[i] = w[i];
    if (t < 32) bs[t] = bias[t];
    __syncthreads();
    int pix = blockIdx.x * 256 + t;           // < NPIX exact
    int b = pix / HW_; int hw = pix % HW_;
    int h = hw / H_, wd = hw % H_;
    float acc[32];
    #pragma unroll
    for (int o = 0; o < 32; o++) acc[o] = bs[o];
    for (int c = 0; c < 3; c++) {
        #pragma unroll
        for (int kr = 0; kr < 3; kr++) {
            int ih = h + kr - 1; if (ih < 0 || ih >= H_) continue;
            #pragma unroll
            for (int kc = 0; kc < 3; kc++) {
                int iw = wd + kc - 1; if (iw < 0 || iw >= H_) continue;
                float xv = x[((b*3 + c)*H_ + ih)*H_ + iw];
                int wi = c*9 + kr*3 + kc;
                #pragma unroll
                for (int o = 0; o < 32; o++) acc[o] += xv * ws[o*27 + wi];
            }
        }
    }
    #pragma unroll
    for (int o = 0; o < 32; o++) g_x1[((b*32 + o)*H_ + h)*H_ + wd] = acc[o];
}

// ---------------------------------------------------------------- conv q,k (direct): 8 oc = {q0-3,k0-3} of head blockIdx.y
// IDENTICAL inner arithmetic to the round-3 passing kernel (argmax-safe).
__global__ __launch_bounds__(256) void k_conv_qk(const float* __restrict__ w) {
    __shared__ float ps[8][34][36];
    __shared__ float wsm[8][8][9];
    int t = threadIdx.x;
    int tile = blockIdx.x;                 // 0..391
    int b = tile / 49; int th = (tile % 49) / 7, tw = tile % 7;
    int h0 = th * 32, w0 = tw * 32;
    int oc0 = blockIdx.y * 12;             // head n's q,k channels
    int r = t >> 3, cg = t & 7;
    float acc[32];
    #pragma unroll
    for (int i = 0; i < 32; i++) acc[i] = 0.f;
    for (int g = 0; g < 4; g++) {
        __syncthreads();
        for (int i = t; i < 8*34*34; i += 256) {
            int ic = i / (34*34); int rr = (i / 34) % 34; int cc = i % 34;
            int ih = h0 + rr - 1, iw = w0 + cc - 1;
            float v = 0.f;
            if (ih >= 0 && ih < H_ && iw >= 0 && iw < H_)
                v = g_x1[((b*32 + g*8 + ic)*H_ + ih)*H_ + iw];
            ps[ic][rr][cc] = v;
        }
        for (int i = t; i < 8*8*9; i += 256) {
            int oc = i / 72; int rem = i % 72; int ic = rem / 9; int tap = rem % 9;
            wsm[oc][ic][tap] = w[((oc0 + oc)*32 + g*8 + ic)*9 + tap];
        }
        __syncthreads();
        #pragma unroll
        for (int ic = 0; ic < 8; ic++) {
            #pragma unroll
            for (int kr = 0; kr < 3; kr++) {
                #pragma unroll
                for (int kc = 0; kc < 3; kc++) {
                    float wv[8], pv[4];
                    #pragma unroll
                    for (int o = 0; o < 8; o++) wv[o] = wsm[o][ic][kr*3 + kc];
                    #pragma unroll
                    for (int p = 0; p < 4; p++) pv[p] = ps[ic][r + kr][cg*4 + p + kc];
                    #pragma unroll
                    for (int o = 0; o < 8; o++)
                        #pragma unroll
                        for (int p = 0; p < 4; p++) acc[o*4 + p] += wv[o] * pv[p];
                }
            }
        }
    }
    int hh = h0 + r;
    #pragma unroll
    for (int o = 0; o < 8; o++)
        #pragma unroll
        for (int p = 0; p < 4; p++)
            g_qkv[((b*96 + oc0 + o)*H_ + hh)*H_ + w0 + cg*4 + p] = acc[o*4 + p];
}

// ---------------------------------------------------------------- conv v via Winograd F(2x2,3x3)
// 4 oc = v channels of head blockIdx.y; v feeds only the gather, so Winograd's
// extra ~1e-6 error is harmless (no argmax sensitivity).
__global__ __launch_bounds__(256, 2) void k_conv_v() {
    __shared__ __align__(16) float ps[8][34][36];
    __shared__ __align__(16) float wt_s[4][8][16];
    int t = threadIdx.x;
    int tile = blockIdx.x;                 // 0..391
    int b = tile / 49; int th = (tile % 49) / 7, tw = tile % 7;
    int h0 = th * 32, w0 = tw * 32;
    int oc0 = blockIdx.y * 12 + 8;         // head n's v channels
    int tr = t >> 4, tc = t & 15;
    int r0 = tr * 2, c0 = tc * 2;
    float m[4][16];
    #pragma unroll
    for (int o = 0; o < 4; o++)
        #pragma unroll
        for (int k = 0; k < 16; k++) m[o][k] = 0.f;

    int lic = t >> 5, ln = t & 31;         // halo loader: warp per ic
    for (int g = 0; g < 4; g++) {
        __syncthreads();
        {
            const float* src = g_x1 + (size_t)(b*32 + g*8 + lic) * HW_;
            int bh = h0 - 1, bw = w0 - 1;
            for (int rr = 0; rr < 34; rr++) {
                int ih = bh + rr;
                bool hok = ((unsigned)ih < (unsigned)H_);
                int iw = bw + ln;
                ps[lic][rr][ln] = (hok && (unsigned)iw < (unsigned)H_) ? src[ih*H_ + iw] : 0.f;
                if (ln < 2) {
                    int iw2 = bw + 32 + ln;
                    ps[lic][rr][32 + ln] = (hok && (unsigned)iw2 < (unsigned)H_) ? src[ih*H_ + iw2] : 0.f;
                }
            }
        }
        for (int i = t; i < 512; i += 256) {
            int o = i >> 7; int ic = (i >> 4) & 7; int k = i & 15;
            wt_s[o][ic][k] = g_wt[((oc0 + o)*32 + g*8 + ic)*16 + k];
        }
        __syncthreads();
        #pragma unroll
        for (int ic = 0; ic < 8; ic++) {
            float d[4][4];
            #pragma unroll
            for (int r = 0; r < 4; r++) {
                float2 a = *(const float2*)&ps[ic][r0 + r][c0];
                float2 e = *(const float2*)&ps[ic][r0 + r][c0 + 2];
                d[r][0] = a.x; d[r][1] = a.y; d[r][2] = e.x; d[r][3] = e.y;
            }
            float bt[4][4];
            #pragma unroll
            for (int c = 0; c < 4; c++) {
                bt[0][c] = d[0][c] - d[2][c];
                bt[1][c] = d[1][c] + d[2][c];
                bt[2][c] = d[2][c] - d[1][c];
                bt[3][c] = d[1][c] - d[3][c];
            }
            float U[16];
            #pragma unroll
            for (int r = 0; r < 4; r++) {
                U[r*4+0] = bt[r][0] - bt[r][2];
                U[r*4+1] = bt[r][1] + bt[r][2];
                U[r*4+2] = bt[r][2] - bt[r][1];
                U[r*4+3] = bt[r][1] - bt[r][3];
            }
            #pragma unroll
            for (int o = 0; o < 4; o++) {
                const float4* wp = (const float4*)wt_s[o][ic];
                float4 wa = wp[0], wb = wp[1], wc = wp[2], wd4 = wp[3];
                m[o][0]  = fmaf(U[0],  wa.x, m[o][0]);
                m[o][1]  = fmaf(U[1],  wa.y, m[o][1]);
                m[o][2]  = fmaf(U[2],  wa.z, m[o][2]);
                m[o][3]  = fmaf(U[3],  wa.w, m[o][3]);
                m[o][4]  = fmaf(U[4],  wb.x, m[o][4]);
                m[o][5]  = fmaf(U[5],  wb.y, m[o][5]);
                m[o][6]  = fmaf(U[6],  wb.z, m[o][6]);
                m[o][7]  = fmaf(U[7],  wb.w, m[o][7]);
                m[o][8]  = fmaf(U[8],  wc.x, m[o][8]);
                m[o][9]  = fmaf(U[9],  wc.y, m[o][9]);
                m[o][10] = fmaf(U[10], wc.z, m[o][10]);
                m[o][11] = fmaf(U[11], wc.w, m[o][11]);
                m[o][12] = fmaf(U[12], wd4.x, m[o][12]);
                m[o][13] = fmaf(U[13], wd4.y, m[o][13]);
                m[o][14] = fmaf(U[14], wd4.z, m[o][14]);
                m[o][15] = fmaf(U[15], wd4.w, m[o][15]);
            }
        }
    }
    #pragma unroll
    for (int o = 0; o < 4; o++) {
        float z0[4], z1[4];
        #pragma unroll
        for (int c = 0; c < 4; c++) {
            z0[c] = m[o][c] + m[o][4+c] + m[o][8+c];
            z1[c] = m[o][4+c] - m[o][8+c] - m[o][12+c];
        }
        float y00 = z0[0] + z0[1] + z0[2];
        float y01 = z0[1] - z0[2] - z0[3];
        float y10 = z1[0] + z1[1] + z1[2];
        float y11 = z1[1] - z1[2] - z1[3];
        float* dst = &g_qkv[((size_t)(b*96 + oc0 + o)*H_ + (h0 + r0))*H_ + (w0 + c0)];
        *(float2*)dst        = make_float2(y00, y01);
        *(float2*)(dst + H_) = make_float2(y10, y11);
    }
}

// ---------------------------------------------------------------- attention argmax + one-hot
// block = (bnd, i-tile of 16); 128 threads (4 warps); warp handles 4 i rows, lane = j within tile
__global__ __launch_bounds__(128) void k_att(const float* __restrict__ gumbel,
                                             float* __restrict__ att) {
    __shared__ float Qs[16][228];
    __shared__ float Ks[32][228];
    int bnd = blockIdx.x;                 // 0..255 = b*32 + n*4 + d
    int it = blockIdx.y;                  // 0..13
    int b = bnd >> 5; int nd = bnd & 31; int n = nd >> 2; int d = nd & 3;
    const float* qbase = g_qkv + (size_t)(b*96 + n*12 + d) * HW_;
    const float* kbase = g_qkv + (size_t)(b*96 + n*12 + 4 + d) * HW_;
    int t = threadIdx.x; int lane = t & 31; int wid = t >> 5;
    int i0 = it * 16;
    for (int i = t; i < 16*H_; i += 128) {
        int rr = i / H_, cc = i % H_;
        Qs[rr][cc] = qbase[(i0 + rr)*H_ + cc];
    }
    float best[4]; int bj[4];
    #pragma unroll
    for (int r = 0; r < 4; r++) { best[r] = -1e30f; bj[r] = 0; }

    for (int jt = 0; jt < H_; jt += 32) {
        __syncthreads();
        for (int i = t; i < 32*H_; i += 128) {
            int rr = i / H_, cc = i % H_;
            Ks[rr][cc] = kbase[(jt + rr)*H_ + cc];
        }
        __syncthreads();
        float acc[4] = {0.f, 0.f, 0.f, 0.f};
        for (int w = 0; w < H_; w += 4) {
            float4 kv = *(const float4*)&Ks[lane][w];
            #pragma unroll
            for (int r = 0; r < 4; r++) {
                float4 qv = *(const float4*)&Qs[wid*4 + r][w];
                acc[r] += kv.x*qv.x + kv.y*qv.y + kv.z*qv.z + kv.w*qv.w;
            }
        }
        int j = jt + lane;
        #pragma unroll
        for (int r = 0; r < 4; r++) {
            int i = i0 + wid*4 + r;
            float v = acc[r]*0.5f + gumbel[((size_t)bnd*H_ + i)*H_ + j];
            if (v > best[r]) { best[r] = v; bj[r] = j; }
        }
    }
    #pragma unroll
    for (int r = 0; r < 4; r++) {
        float v = best[r]; int j = bj[r];
        #pragma unroll
        for (int off = 16; off; off >>= 1) {
            float v2 = __shfl_down_sync(0xffffffffu, v, off);
            int   j2 = __shfl_down_sync(0xffffffffu, j, off);
            if (v2 > v || (v2 == v && j2 < j)) { v = v2; j = j2; }
        }
        if (lane == 0) {
            int i = i0 + wid*4 + r;
            g_jidx[bnd*H_ + i] = j;
            att[((size_t)bnd*H_ + i)*H_ + j] = 1.0f;
        }
    }
}

// ---------------------------------------------------------------- gather v rows + fused 1x1 convs + BN partial sums
// block per (b, i); 224 threads (one per w)
__global__ __launch_bounds__(224) void k_gather_proj() {
    __shared__ float wcs[1024];
    __shared__ float bcs[32];
    __shared__ int   js[32];
    __shared__ float rs[32][7];
    __shared__ float rq[32][7];
    int b = blockIdx.x / H_; int i = blockIdx.x % H_;
    int t = threadIdx.x;
    for (int k = t; k < 1024; k += 224) wcs[k] = g_wc[k];
    if (t < 32) {
        bcs[t] = g_bc[t];
        js[t] = g_jidx[(b*32 + t)*H_ + i];   // t = n*4+d
    }
    __syncthreads();
    float a[32];
    #pragma unroll
    for (int c = 0; c < 32; c++) {
        int n = c >> 2, d = c & 3;
        a[c] = g_qkv[((size_t)(b*96 + n*12 + 8 + d)*H_ + js[c])*H_ + t];
    }
    float out[32];
    #pragma unroll
    for (int o = 0; o < 32; o++) {
        float s = bcs[o];
        #pragma unroll
        for (int c = 0; c < 32; c++) s += wcs[o*32 + c] * a[c];
        out[o] = s;
        g_A2[((size_t)(b*32 + o)*H_ + i)*H_ + t] = s;
    }
    int wid = t >> 5, lane = t & 31;
    #pragma unroll
    for (int o = 0; o < 32; o++) {
        float s = out[o], q = out[o]*out[o];
        #pragma unroll
        for (int off = 16; off; off >>= 1) {
            s += __shfl_down_sync(0xffffffffu, s, off);
            q += __shfl_down_sync(0xffffffffu, q, off);
        }
        if (lane == 0) { rs[o][wid] = s; rq[o][wid] = q; }
    }
    __syncthreads();
    if (t < 32) {
        float s = 0.f, q = 0.f;
        #pragma unroll
        for (int k = 0; k < 7; k++) { s += rs[t][k]; q += rq[t][k]; }
        atomicAdd(&g_sum[t], s);
        atomicAdd(&g_sq[t], q);
    }
}

// ---------------------------------------------------------------- BN + SiLU + residual
__global__ __launch_bounds__(256) void k_final(const float* __restrict__ gamma,
                                               const float* __restrict__ beta,
                                               float* __restrict__ outp) {
    int idx = blockIdx.x * 256 + threadIdx.x;   // < X1_N exact
    int c = (idx / HW_) & 31;
    const float inv_n = 1.f / (float)NPIX;
    float mean = g_sum[c] * inv_n;
    float var = g_sq[c] * inv_n - mean*mean;
    float v = (g_A2[idx] - mean) * rsqrtf(var + 1e-5f) * gamma[c] + beta[c];
    v = v / (1.f + expf(-v));
    outp[idx] = v + g_x1[idx];
}

// ---------------------------------------------------------------- launch
extern "C" void kernel_launch(void* const* d_in, const int* in_sizes, int n_in,
                              void* d_out, int out_size) {
    const float* x      = (const float*)d_in[0];
    const float* gumbel = (const float*)d_in[1];
    const float* in_w   = (const float*)d_in[2];
    const float* in_b   = (const float*)d_in[3];
    const float* qkv_w  = (const float*)d_in[4];
    const float* proj_w = (const float*)d_in[5];
    const float* proj_b = (const float*)d_in[6];
    const float* upd_w  = (const float*)d_in[7];
    const float* upd_b  = (const float*)d_in[8];
    const float* bn_g   = (const float*)d_in[9];
    const float* bn_b   = (const float*)d_in[10];
    float* outp = (float*)d_out;
    float* att  = outp + X1_N;                 // (out, att) concatenated

    k_prep<<<1, 1024>>>(upd_w, proj_w, proj_b, upd_b);
    k_wprep<<<12, 256>>>(qkv_w);
    k_zero<<<ATT_N/4/256, 256>>>((float4*)att);
    k_conv_in<<<NPIX/256, 256>>>(x, in_w, in_b);
    k_conv_qk<<<dim3(392, 8), 256>>>(qkv_w);
    k_conv_v<<<dim3(392, 8), 256>>>();
    k_att<<<dim3(256, 14), 128>>>(gumbel, att);
    k_gather_proj<<<B_*H_, 224>>>();
    k_final<<<X1_N/256, 256>>>(bn_g, bn_b, outp);
}

// round 9
// speedup vs baseline: 1.5482x; 1.5482x over previous
#include <cuda_runtime.h>
#include <cstdint>

// Problem constants
#define B_   8
#define H_   224
#define HW_  (H_*H_)          // 50176
#define OC_  32
#define NH_  8
#define HD_  4
#define NPIX (B_*HW_)         // 401408
#define X1_N (B_*OC_*HW_)     // 12845056
#define QKV_N (B_*96*HW_)     // 38535168
#define ATT_N (B_*NH_*HD_*H_*H_) // 12845056

// Scratch (static device globals; no allocation allowed)
__device__ float g_x1[X1_N];
__device__ float g_qkv[QKV_N];
__device__ float g_A2[X1_N];
__device__ int   g_jidx[B_*NH_*HD_*H_];   // 57344
__device__ float g_wc[32*32];
__device__ float g_bc[32];
__device__ float g_sum[32];
__device__ float g_sq[32];
__device__ float g_wt[96*32*16];          // winograd-transformed qkv weights (only v rows used)

// ---------------------------------------------------------------- prep
__global__ void k_prep(const float* __restrict__ upd_w, const float* __restrict__ proj_w,
                       const float* __restrict__ proj_b, const float* __restrict__ upd_b) {
    int t = threadIdx.x;            // 1024 threads
    int o = t >> 5, c = t & 31;
    float s = 0.f;
    #pragma unroll
    for (int m = 0; m < 32; m++) s += upd_w[o*32+m] * proj_w[m*32+c];
    g_wc[o*32+c] = s;
    if (c == 0) {
        float bsum = upd_b[o];
        #pragma unroll
        for (int m = 0; m < 32; m++) bsum += upd_w[o*32+m] * proj_b[m];
        g_bc[o] = bsum;
    }
    if (t < 32) { g_sum[t] = 0.f; g_sq[t] = 0.f; }
}

// ---------------------------------------------------------------- winograd weight transform
__global__ void k_wprep(const float* __restrict__ qkv_w) {
    int id = blockIdx.x * 256 + threadIdx.x;   // 12*256 = 3072 exact
    const float* gp = qkv_w + id * 9;
    float g0[3][3];
    #pragma unroll
    for (int r = 0; r < 3; r++)
        #pragma unroll
        for (int c = 0; c < 3; c++) g0[r][c] = gp[r*3 + c];
    float P[4][3];
    #pragma unroll
    for (int c = 0; c < 3; c++) {
        P[0][c] = g0[0][c];
        P[1][c] = 0.5f*(g0[0][c] + g0[1][c] + g0[2][c]);
        P[2][c] = 0.5f*(g0[0][c] - g0[1][c] + g0[2][c]);
        P[3][c] = g0[2][c];
    }
    #pragma unroll
    for (int r = 0; r < 4; r++) {
        g_wt[id*16 + r*4 + 0] = P[r][0];
        g_wt[id*16 + r*4 + 1] = 0.5f*(P[r][0] + P[r][1] + P[r][2]);
        g_wt[id*16 + r*4 + 2] = 0.5f*(P[r][0] - P[r][1] + P[r][2]);
        g_wt[id*16 + r*4 + 3] = P[r][2];
    }
}

// ---------------------------------------------------------------- zero att
__global__ void k_zero(float4* __restrict__ p) {
    int i = blockIdx.x * 256 + threadIdx.x;   // grid covers ATT_N/4 exactly
    p[i] = make_float4(0.f, 0.f, 0.f, 0.f);
}

// ---------------------------------------------------------------- conv_in: 3->32, 3x3, pad 1 (2 px/thread)
__global__ __launch_bounds__(256) void k_conv_in(const float* __restrict__ x,
                                                 const float* __restrict__ w,
                                                 const float* __restrict__ bias) {
    __shared__ float ws[32*27];
    __shared__ float bs[32];
    int t = threadIdx.x;
    for (int i = t; i < 864; i += 256) ws[i] = w[i];
    if (t < 32) bs[t] = bias[t];
    __syncthreads();
    int p2 = blockIdx.x * 256 + t;            // < NPIX/2 exact
    int pix = p2 * 2;
    int b = pix / HW_; int hw = pix % HW_;
    int h = hw / H_, wd = hw % H_;            // wd even
    float acc0[32], acc1[32];
    #pragma unroll
    for (int o = 0; o < 32; o++) { acc0[o] = bs[o]; acc1[o] = bs[o]; }
    for (int c = 0; c < 3; c++) {
        const float* xc = x + ((size_t)(b*3 + c))*HW_;
        #pragma unroll
        for (int kr = 0; kr < 3; kr++) {
            int ih = h + kr - 1; if (ih < 0 || ih >= H_) continue;
            const float* row = xc + ih*H_;
            float xm1 = (wd - 1 >= 0) ? row[wd-1] : 0.f;
            float x0  = row[wd];
            float x1  = row[wd+1];
            float x2  = (wd + 2 < H_) ? row[wd+2] : 0.f;
            float a0[3] = {xm1, x0, x1};
            float a1[3] = {x0, x1, x2};
            #pragma unroll
            for (int kc = 0; kc < 3; kc++) {
                int wi = c*9 + kr*3 + kc;
                float v0 = a0[kc], v1 = a1[kc];
                #pragma unroll
                for (int o = 0; o < 32; o++) {
                    float wv = ws[o*27 + wi];
                    acc0[o] = fmaf(wv, v0, acc0[o]);
                    acc1[o] = fmaf(wv, v1, acc1[o]);
                }
            }
        }
    }
    #pragma unroll
    for (int o = 0; o < 32; o++)
        *(float2*)&g_x1[((size_t)(b*32 + o)*H_ + h)*H_ + wd] = make_float2(acc0[o], acc1[o]);
}

// ---------------------------------------------------------------- conv q,k (direct): 8 oc = {q0-3,k0-3} of head blockIdx.y
// IDENTICAL inner arithmetic to the round-3 passing kernel (argmax-safe).
__global__ __launch_bounds__(256) void k_conv_qk(const float* __restrict__ w) {
    __shared__ float ps[8][34][36];
    __shared__ float wsm[8][8][9];
    int t = threadIdx.x;
    int tile = blockIdx.x;                 // 0..391
    int b = tile / 49; int th = (tile % 49) / 7, tw = tile % 7;
    int h0 = th * 32, w0 = tw * 32;
    int oc0 = blockIdx.y * 12;             // head n's q,k channels
    int r = t >> 3, cg = t & 7;
    float acc[32];
    #pragma unroll
    for (int i = 0; i < 32; i++) acc[i] = 0.f;
    for (int g = 0; g < 4; g++) {
        __syncthreads();
        for (int i = t; i < 8*34*34; i += 256) {
            int ic = i / (34*34); int rr = (i / 34) % 34; int cc = i % 34;
            int ih = h0 + rr - 1, iw = w0 + cc - 1;
            float v = 0.f;
            if (ih >= 0 && ih < H_ && iw >= 0 && iw < H_)
                v = g_x1[((b*32 + g*8 + ic)*H_ + ih)*H_ + iw];
            ps[ic][rr][cc] = v;
        }
        for (int i = t; i < 8*8*9; i += 256) {
            int oc = i / 72; int rem = i % 72; int ic = rem / 9; int tap = rem % 9;
            wsm[oc][ic][tap] = w[((oc0 + oc)*32 + g*8 + ic)*9 + tap];
        }
        __syncthreads();
        #pragma unroll
        for (int ic = 0; ic < 8; ic++) {
            #pragma unroll
            for (int kr = 0; kr < 3; kr++) {
                #pragma unroll
                for (int kc = 0; kc < 3; kc++) {
                    float wv[8], pv[4];
                    #pragma unroll
                    for (int o = 0; o < 8; o++) wv[o] = wsm[o][ic][kr*3 + kc];
                    #pragma unroll
                    for (int p = 0; p < 4; p++) pv[p] = ps[ic][r + kr][cg*4 + p + kc];
                    #pragma unroll
                    for (int o = 0; o < 8; o++)
                        #pragma unroll
                        for (int p = 0; p < 4; p++) acc[o*4 + p] += wv[o] * pv[p];
                }
            }
        }
    }
    int hh = h0 + r;
    #pragma unroll
    for (int o = 0; o < 8; o++)
        #pragma unroll
        for (int p = 0; p < 4; p++)
            g_qkv[((b*96 + oc0 + o)*H_ + hh)*H_ + w0 + cg*4 + p] = acc[o*4 + p];
}

// ---------------------------------------------------------------- conv v via Winograd F(2x2,3x3)
__global__ __launch_bounds__(256, 2) void k_conv_v() {
    __shared__ __align__(16) float ps[8][34][36];
    __shared__ __align__(16) float wt_s[4][8][16];
    int t = threadIdx.x;
    int tile = blockIdx.x;                 // 0..391
    int b = tile / 49; int th = (tile % 49) / 7, tw = tile % 7;
    int h0 = th * 32, w0 = tw * 32;
    int oc0 = blockIdx.y * 12 + 8;         // head n's v channels
    int tr = t >> 4, tc = t & 15;
    int r0 = tr * 2, c0 = tc * 2;
    float m[4][16];
    #pragma unroll
    for (int o = 0; o < 4; o++)
        #pragma unroll
        for (int k = 0; k < 16; k++) m[o][k] = 0.f;

    int lic = t >> 5, ln = t & 31;         // halo loader: warp per ic
    for (int g = 0; g < 4; g++) {
        __syncthreads();
        {
            const float* src = g_x1 + (size_t)(b*32 + g*8 + lic) * HW_;
            int bh = h0 - 1, bw = w0 - 1;
            for (int rr = 0; rr < 34; rr++) {
                int ih = bh + rr;
                bool hok = ((unsigned)ih < (unsigned)H_);
                int iw = bw + ln;
                ps[lic][rr][ln] = (hok && (unsigned)iw < (unsigned)H_) ? src[ih*H_ + iw] : 0.f;
                if (ln < 2) {
                    int iw2 = bw + 32 + ln;
                    ps[lic][rr][32 + ln] = (hok && (unsigned)iw2 < (unsigned)H_) ? src[ih*H_ + iw2] : 0.f;
                }
            }
        }
        for (int i = t; i < 512; i += 256) {
            int o = i >> 7; int ic = (i >> 4) & 7; int k = i & 15;
            wt_s[o][ic][k] = g_wt[((oc0 + o)*32 + g*8 + ic)*16 + k];
        }
        __syncthreads();
        #pragma unroll
        for (int ic = 0; ic < 8; ic++) {
            float d[4][4];
            #pragma unroll
            for (int r = 0; r < 4; r++) {
                float2 a = *(const float2*)&ps[ic][r0 + r][c0];
                float2 e = *(const float2*)&ps[ic][r0 + r][c0 + 2];
                d[r][0] = a.x; d[r][1] = a.y; d[r][2] = e.x; d[r][3] = e.y;
            }
            float bt[4][4];
            #pragma unroll
            for (int c = 0; c < 4; c++) {
                bt[0][c] = d[0][c] - d[2][c];
                bt[1][c] = d[1][c] + d[2][c];
                bt[2][c] = d[2][c] - d[1][c];
                bt[3][c] = d[1][c] - d[3][c];
            }
            float U[16];
            #pragma unroll
            for (int r = 0; r < 4; r++) {
                U[r*4+0] = bt[r][0] - bt[r][2];
                U[r*4+1] = bt[r][1] + bt[r][2];
                U[r*4+2] = bt[r][2] - bt[r][1];
                U[r*4+3] = bt[r][1] - bt[r][3];
            }
            #pragma unroll
            for (int o = 0; o < 4; o++) {
                const float4* wp = (const float4*)wt_s[o][ic];
                float4 wa = wp[0], wb = wp[1], wc = wp[2], wd4 = wp[3];
                m[o][0]  = fmaf(U[0],  wa.x, m[o][0]);
                m[o][1]  = fmaf(U[1],  wa.y, m[o][1]);
                m[o][2]  = fmaf(U[2],  wa.z, m[o][2]);
                m[o][3]  = fmaf(U[3],  wa.w, m[o][3]);
                m[o][4]  = fmaf(U[4],  wb.x, m[o][4]);
                m[o][5]  = fmaf(U[5],  wb.y, m[o][5]);
                m[o][6]  = fmaf(U[6],  wb.z, m[o][6]);
                m[o][7]  = fmaf(U[7],  wb.w, m[o][7]);
                m[o][8]  = fmaf(U[8],  wc.x, m[o][8]);
                m[o][9]  = fmaf(U[9],  wc.y, m[o][9]);
                m[o][10] = fmaf(U[10], wc.z, m[o][10]);
                m[o][11] = fmaf(U[11], wc.w, m[o][11]);
                m[o][12] = fmaf(U[12], wd4.x, m[o][12]);
                m[o][13] = fmaf(U[13], wd4.y, m[o][13]);
                m[o][14] = fmaf(U[14], wd4.z, m[o][14]);
                m[o][15] = fmaf(U[15], wd4.w, m[o][15]);
            }
        }
    }
    #pragma unroll
    for (int o = 0; o < 4; o++) {
        float z0[4], z1[4];
        #pragma unroll
        for (int c = 0; c < 4; c++) {
            z0[c] = m[o][c] + m[o][4+c] + m[o][8+c];
            z1[c] = m[o][4+c] - m[o][8+c] - m[o][12+c];
        }
        float y00 = z0[0] + z0[1] + z0[2];
        float y01 = z0[1] - z0[2] - z0[3];
        float y10 = z1[0] + z1[1] + z1[2];
        float y11 = z1[1] - z1[2] - z1[3];
        float* dst = &g_qkv[((size_t)(b*96 + oc0 + o)*H_ + (h0 + r0))*H_ + (w0 + c0)];
        *(float2*)dst        = make_float2(y00, y01);
        *(float2*)(dst + H_) = make_float2(y10, y11);
    }
}

// ---------------------------------------------------------------- attention argmax + one-hot
// block = (bnd, i-tile of 32); 256 threads (8 warps); warp handles 4 i rows,
// lanes 0-15 / 16-31 split the w-sum for 16 j's per K chunk.
__global__ __launch_bounds__(256) void k_att(const float* __restrict__ gumbel,
                                             float* __restrict__ att) {
    __shared__ float Qs[32][228];
    __shared__ float Ks[16][228];
    int bnd = blockIdx.x;                 // 0..255 = b*32 + n*4 + d
    int it = blockIdx.y;                  // 0..6
    int b = bnd >> 5; int nd = bnd & 31; int n = nd >> 2; int d = nd & 3;
    const float* qbase = g_qkv + (size_t)(b*96 + n*12 + d) * HW_;
    const float* kbase = g_qkv + (size_t)(b*96 + n*12 + 4 + d) * HW_;
    int t = threadIdx.x; int lane = t & 31; int wid = t >> 5;
    int i0 = it * 32;
    for (int i = t; i < 32*56; i += 256) {
        int rr = i / 56, c4 = i % 56;
        *(float4*)&Qs[rr][c4*4] = ((const float4*)(qbase + (size_t)(i0 + rr)*H_))[c4];
    }
    float best[4]; int bj[4];
    #pragma unroll
    for (int r = 0; r < 4; r++) { best[r] = -1e30f; bj[r] = 0; }

    int jj = lane & 15;
    int wbase = (lane >> 4) * 112;
    for (int jt = 0; jt < H_; jt += 16) {
        __syncthreads();
        for (int i = t; i < 16*56; i += 256) {
            int rr = i / 56, c4 = i % 56;
            *(float4*)&Ks[rr][c4*4] = ((const float4*)(kbase + (size_t)(jt + rr)*H_))[c4];
        }
        __syncthreads();
        float acc[4] = {0.f, 0.f, 0.f, 0.f};
        for (int w = 0; w < 112; w += 4) {
            float4 kv = *(const float4*)&Ks[jj][wbase + w];
            #pragma unroll
            for (int r = 0; r < 4; r++) {
                float4 qv = *(const float4*)&Qs[wid*4 + r][wbase + w];
                acc[r] += kv.x*qv.x + kv.y*qv.y + kv.z*qv.z + kv.w*qv.w;
            }
        }
        int j = jt + jj;
        #pragma unroll
        for (int r = 0; r < 4; r++) {
            float dot = acc[r] + __shfl_xor_sync(0xffffffffu, acc[r], 16);
            int i = i0 + wid*4 + r;
            float v = dot*0.5f + gumbel[((size_t)bnd*H_ + i)*H_ + j];
            if (v > best[r]) { best[r] = v; bj[r] = j; }
        }
    }
    #pragma unroll
    for (int r = 0; r < 4; r++) {
        float v = best[r]; int j = bj[r];
        #pragma unroll
        for (int off = 16; off; off >>= 1) {
            float v2 = __shfl_down_sync(0xffffffffu, v, off);
            int   j2 = __shfl_down_sync(0xffffffffu, j, off);
            if (v2 > v || (v2 == v && j2 < j)) { v = v2; j = j2; }
        }
        if (lane == 0) {
            int i = i0 + wid*4 + r;
            g_jidx[bnd*H_ + i] = j;
            att[((size_t)bnd*H_ + i)*H_ + j] = 1.0f;
        }
    }
}

// ---------------------------------------------------------------- gather v rows + fused 1x1 convs + BN partial sums
// block per (b, i); 224 threads (one per w)
__global__ __launch_bounds__(224) void k_gather_proj() {
    __shared__ float wcs[1024];
    __shared__ float bcs[32];
    __shared__ int   js[32];
    __shared__ float rs[32][7];
    __shared__ float rq[32][7];
    int b = blockIdx.x / H_; int i = blockIdx.x % H_;
    int t = threadIdx.x;
    for (int k = t; k < 1024; k += 224) wcs[k] = g_wc[k];
    if (t < 32) {
        bcs[t] = g_bc[t];
        js[t] = g_jidx[(b*32 + t)*H_ + i];   // t = n*4+d
    }
    __syncthreads();
    float a[32];
    #pragma unroll
    for (int c = 0; c < 32; c++) {
        int n = c >> 2, d = c & 3;
        a[c] = g_qkv[((size_t)(b*96 + n*12 + 8 + d)*H_ + js[c])*H_ + t];
    }
    float out[32];
    #pragma unroll
    for (int o = 0; o < 32; o++) {
        float s = bcs[o];
        #pragma unroll
        for (int c = 0; c < 32; c++) s += wcs[o*32 + c] * a[c];
        out[o] = s;
        g_A2[((size_t)(b*32 + o)*H_ + i)*H_ + t] = s;
    }
    int wid = t >> 5, lane = t & 31;
    #pragma unroll
    for (int o = 0; o < 32; o++) {
        float s = out[o], q = out[o]*out[o];
        #pragma unroll
        for (int off = 16; off; off >>= 1) {
            s += __shfl_down_sync(0xffffffffu, s, off);
            q += __shfl_down_sync(0xffffffffu, q, off);
        }
        if (lane == 0) { rs[o][wid] = s; rq[o][wid] = q; }
    }
    __syncthreads();
    if (t < 32) {
        float s = 0.f, q = 0.f;
        #pragma unroll
        for (int k = 0; k < 7; k++) { s += rs[t][k]; q += rq[t][k]; }
        atomicAdd(&g_sum[t], s);
        atomicAdd(&g_sq[t], q);
    }
}

// ---------------------------------------------------------------- BN + SiLU + residual
__global__ __launch_bounds__(256) void k_final(const float* __restrict__ gamma,
                                               const float* __restrict__ beta,
                                               float* __restrict__ outp) {
    int idx = blockIdx.x * 256 + threadIdx.x;   // < X1_N exact
    int c = (idx / HW_) & 31;
    const float inv_n = 1.f / (float)NPIX;
    float mean = g_sum[c] * inv_n;
    float var = g_sq[c] * inv_n - mean*mean;
    float v = (g_A2[idx] - mean) * rsqrtf(var + 1e-5f) * gamma[c] + beta[c];
    v = v / (1.f + expf(-v));
    outp[idx] = v + g_x1[idx];
}

// ---------------------------------------------------------------- launch
extern "C" void kernel_launch(void* const* d_in, const int* in_sizes, int n_in,
                              void* d_out, int out_size) {
    const float* x      = (const float*)d_in[0];
    const float* gumbel = (const float*)d_in[1];
    const float* in_w   = (const float*)d_in[2];
    const float* in_b   = (const float*)d_in[3];
    const float* qkv_w  = (const float*)d_in[4];
    const float* proj_w = (const float*)d_in[5];
    const float* proj_b = (const float*)d_in[6];
    const float* upd_w  = (const float*)d_in[7];
    const float* upd_b  = (const float*)d_in[8];
    const float* bn_g   = (const float*)d_in[9];
    const float* bn_b   = (const float*)d_in[10];
    float* outp = (float*)d_out;
    float* att  = outp + X1_N;                 // (out, att) concatenated

    k_prep<<<1, 1024>>>(upd_w, proj_w, proj_b, upd_b);
    k_wprep<<<12, 256>>>(qkv_w);
    k_zero<<<ATT_N/4/256, 256>>>((float4*)att);
    k_conv_in<<<NPIX/2/256, 256>>>(x, in_w, in_b);
    k_conv_qk<<<dim3(392, 8), 256>>>(qkv_w);
    k_conv_v<<<dim3(392, 8), 256>>>();
    k_att<<<dim3(256, 7), 256>>>(gumbel, att);
    k_gather_proj<<<B_*H_, 224>>>();
    k_final<<<X1_N/256, 256>>>(bn_g, bn_b, outp);
}